// round 15
// baseline (speedup 1.0000x reference)
#include <cuda_runtime.h>
#include <cstdint>

// CapsuleRouting R14: single-buffered register streaming (no smem u staging)
//  - CTA = (b, x-tile of 8); 144 CTAs, 256 threads; warp owns 18 B
//  - ureg[16] float4 single buffer; reload of chunk j+1 interleaved into
//    accumulate(j) (each reg reloaded right after last use) -> no spill
//  - v read from smem (PLANE=132: per-phase conflict-free LDS.128)
//  - serpentine pass order (pass 1 reversed): ~335MB DRAM + hot cross-pass preload
//  - r eliminated (logits linear in v: pass2 dots against w = v0+v1); `a` ignored

#define C_N   16
#define P_N   16
#define F2    144
#define XT    8
#define NTILE 18
#define NW    8
#define BPW   18
#define PLANE 132                     // conflict-free v/partial row stride
#define PART_FL (C_N * PLANE)         // 2112 floats per warp partial
#define V_OFF   (NW * PART_FL)        // 16896
#define SMEM_FL (V_OFF + PART_FL)     // 19008
#define SMEM_BYTES (SMEM_FL * 4)      // 76032
#define BSTRIDE (C_N * P_N * F2)      // 36864 floats per B
#define V_ELEMS (8 * C_N * P_N * F2)  // 294912

// serpentine B order: pass 1 reversed
#define BIDX(pass, j) (((pass) == 1) ? (BPW - 1 - (j)) : (j))

__global__ void __launch_bounds__(256, 1)
caps_route_kernel(const float* __restrict__ u, float* __restrict__ out) {
    extern __shared__ float sm[];
    float* v_s = sm + V_OFF;

    const int t = threadIdx.x;
    const int w = t >> 5, lane = t & 31;
    const int Cc = lane & 15, zh = lane >> 4;

    const int b  = blockIdx.x / NTILE;
    const int x0 = (blockIdx.x % NTILE) * XT;

    // lane's global base: warp B-slice + C row block + x-quad
    const float* laneg = u + ((size_t)b * 144 + w * BPW) * BSTRIDE
                           + (size_t)Cc * P_N * F2 + x0 + zh * 4;
    float* wpart = sm + w * PART_FL;
    const int ld_off = Cc * PLANE + zh * 4;    // + p*8

    float4 ureg[16], sreg[16];
#pragma unroll
    for (int p = 0; p < 16; p++)               // pass0 chunk0 preload
        ureg[p] = *(const float4*)(laneg + p * F2);

    for (int pass = 0; pass < 3; pass++) {
#pragma unroll
        for (int p = 0; p < 16; p++) sreg[p] = make_float4(0.f, 0.f, 0.f, 0.f);

        for (int j = 0; j < BPW; j++) {
            const bool rel = (j + 1 < BPW);
            const float* gn = laneg
                + (size_t)BIDX(pass, rel ? j + 1 : 0) * BSTRIDE;

            if (pass == 0) {
#pragma unroll
                for (int p = 0; p < 16; p++) {
                    sreg[p].x += ureg[p].x; sreg[p].y += ureg[p].y;
                    sreg[p].z += ureg[p].z; sreg[p].w += ureg[p].w;
                    if (rel) ureg[p] = *(const float4*)(gn + p * F2);
                }
            } else {
                // dot over p against v (smem, conflict-free)
                float4 d = make_float4(0.f, 0.f, 0.f, 0.f);
#pragma unroll
                for (int p = 0; p < 16; p++) {
                    float4 v4 = *(const float4*)&v_s[ld_off + p * 8];
                    d.x = fmaf(ureg[p].x, v4.x, d.x);
                    d.y = fmaf(ureg[p].y, v4.y, d.y);
                    d.z = fmaf(ureg[p].z, v4.z, d.z);
                    d.w = fmaf(ureg[p].w, v4.w, d.w);
                }
                // softmax over C: 16-lane shuffle groups, 4 chains ILP
                float4 e = make_float4(__expf(d.x), __expf(d.y),
                                       __expf(d.z), __expf(d.w));
                float4 ss = e;
#pragma unroll
                for (int m = 1; m < 16; m <<= 1) {
                    ss.x += __shfl_xor_sync(0xffffffffu, ss.x, m);
                    ss.y += __shfl_xor_sync(0xffffffffu, ss.y, m);
                    ss.z += __shfl_xor_sync(0xffffffffu, ss.z, m);
                    ss.w += __shfl_xor_sync(0xffffffffu, ss.w, m);
                }
                float4 cc = make_float4(__fdividef(e.x, ss.x),
                                        __fdividef(e.y, ss.y),
                                        __fdividef(e.z, ss.z),
                                        __fdividef(e.w, ss.w));
                // accumulate; reload ureg[p] immediately after its last use
#pragma unroll
                for (int p = 0; p < 16; p++) {
                    sreg[p].x = fmaf(cc.x, ureg[p].x, sreg[p].x);
                    sreg[p].y = fmaf(cc.y, ureg[p].y, sreg[p].y);
                    sreg[p].z = fmaf(cc.z, ureg[p].z, sreg[p].z);
                    sreg[p].w = fmaf(cc.w, ureg[p].w, sreg[p].w);
                    if (rel) ureg[p] = *(const float4*)(gn + p * F2);
                }
            }
        }

        // ---- per-warp partial s -> own smem region ----
        if (pass == 0) {
#pragma unroll
            for (int p = 0; p < 16; p++) {
                sreg[p].x *= 0.0625f; sreg[p].y *= 0.0625f;
                sreg[p].z *= 0.0625f; sreg[p].w *= 0.0625f;
            }
        }
#pragma unroll
        for (int p = 0; p < 16; p++)
            *(float4*)&wpart[ld_off + p * 8] = sreg[p];

        if (pass < 2) {   // next pass chunk0 (serpentine: just-used B, L1/L2-hot)
            const float* g0 = laneg + (size_t)BIDX(pass + 1, 0) * BSTRIDE;
#pragma unroll
            for (int p = 0; p < 16; p++)
                ureg[p] = *(const float4*)(g0 + p * F2);
        }
        __syncthreads();

        // ---- cross-warp reduce + squash: thread t = (Cc2 = t>>4, p2 = t&15)
        {
            const int Cc2 = t >> 4, p2 = t & 15;
            const int roff = Cc2 * PLANE + p2 * 8;
            float4 sa = make_float4(0.f, 0.f, 0.f, 0.f);   // z 0..3
            float4 sb = make_float4(0.f, 0.f, 0.f, 0.f);   // z 4..7
#pragma unroll
            for (int w2 = 0; w2 < NW; w2++) {
                float4 a4 = *(const float4*)&sm[w2 * PART_FL + roff];
                float4 b4 = *(const float4*)&sm[w2 * PART_FL + roff + 4];
                sa.x += a4.x; sa.y += a4.y; sa.z += a4.z; sa.w += a4.w;
                sb.x += b4.x; sb.y += b4.y; sb.z += b4.z; sb.w += b4.w;
            }
            float4 na = make_float4(sa.x * sa.x, sa.y * sa.y,
                                    sa.z * sa.z, sa.w * sa.w);
            float4 nb = make_float4(sb.x * sb.x, sb.y * sb.y,
                                    sb.z * sb.z, sb.w * sb.w);
#pragma unroll
            for (int m = 1; m < 16; m <<= 1) {
                na.x += __shfl_xor_sync(0xffffffffu, na.x, m);
                na.y += __shfl_xor_sync(0xffffffffu, na.y, m);
                na.z += __shfl_xor_sync(0xffffffffu, na.z, m);
                na.w += __shfl_xor_sync(0xffffffffu, na.w, m);
                nb.x += __shfl_xor_sync(0xffffffffu, nb.x, m);
                nb.y += __shfl_xor_sync(0xffffffffu, nb.y, m);
                nb.z += __shfl_xor_sync(0xffffffffu, nb.z, m);
                nb.w += __shfl_xor_sync(0xffffffffu, nb.w, m);
            }
            float4 ka = make_float4(sqrtf(na.x) / (1.f + na.x),
                                    sqrtf(na.y) / (1.f + na.y),
                                    sqrtf(na.z) / (1.f + na.z),
                                    sqrtf(na.w) / (1.f + na.w));
            float4 kb = make_float4(sqrtf(nb.x) / (1.f + nb.x),
                                    sqrtf(nb.y) / (1.f + nb.y),
                                    sqrtf(nb.z) / (1.f + nb.z),
                                    sqrtf(nb.w) / (1.f + nb.w));
            float4 va = make_float4(sa.x * ka.x, sa.y * ka.y,
                                    sa.z * ka.z, sa.w * ka.w);
            float4 vb = make_float4(sb.x * kb.x, sb.y * kb.y,
                                    sb.z * kb.z, sb.w * kb.w);

            if (pass < 2) {
                if (pass == 1) {   // store w = v0 + v1 (logits linear in v)
                    float4 oa = *(const float4*)&v_s[roff];
                    float4 ob = *(const float4*)&v_s[roff + 4];
                    va.x += oa.x; va.y += oa.y; va.z += oa.z; va.w += oa.w;
                    vb.x += ob.x; vb.y += ob.y; vb.z += ob.z; vb.w += ob.w;
                }
                *(float4*)&v_s[roff]     = va;
                *(float4*)&v_s[roff + 4] = vb;
            } else {
                float* og = out + (((size_t)(b * C_N + Cc2)) * P_N + p2) * F2 + x0;
                *(float4*)og       = va;
                *(float4*)(og + 4) = vb;
                if (p2 == 0) {
                    float* oa = out + (size_t)V_ELEMS
                              + ((size_t)(b * C_N + Cc2)) * F2 + x0;
                    *(float4*)oa = make_float4(na.x / (1.f + na.x),
                                               na.y / (1.f + na.y),
                                               na.z / (1.f + na.z),
                                               na.w / (1.f + na.w));
                    *(float4*)(oa + 4) = make_float4(nb.x / (1.f + nb.x),
                                                     nb.y / (1.f + nb.y),
                                                     nb.z / (1.f + nb.z),
                                                     nb.w / (1.f + nb.w));
                }
            }
        }
        __syncthreads();   // v_s visible before next pass's dot reads it
    }
}

extern "C" void kernel_launch(void* const* d_in, const int* in_sizes, int n_in,
                              void* d_out, int out_size) {
    const float* u = (const float*)d_in[0];   // (8,144,16,16,12,12) f32
    float* out = (float*)d_out;               // v (8,16,16,144) then a_out (8,16,144)

    cudaFuncSetAttribute(caps_route_kernel,
                         cudaFuncAttributeMaxDynamicSharedMemorySize, SMEM_BYTES);
    caps_route_kernel<<<8 * NTILE, 256, SMEM_BYTES>>>(u, out);
}

// round 16
// speedup vs baseline: 1.1778x; 1.1778x over previous
#include <cuda_runtime.h>
#include <cuda.h>
#include <dlfcn.h>
#include <cstdint>

// CapsuleRouting R15: TMA-fed per-warp pipelines (fallback: R13 cp.async kernel)
//  - box (x8, C16, p16) per B-chunk -> smem [p][C][x8], conflict-free LDS
//  - one UTMALDG per chunk: no per-lane L1tex wavefronts (the R7-R14 binder)
//  - 8 warps, NSTG=3, per-(warp,stage) mbarrier, phase=(j/3)&1
//  - serpentine pass order; SW-pipelined dot/softmax; w=v0+v1; `a` ignored

#define C_N   16
#define P_N   16
#define F2    144
#define XT    8
#define NTILE 18
#define NW    8
#define BPW   18
#define NSTG  3
// TMA kernel smem (floats)
#define TSTG_FL   2048                   // one box: 16p x 16C x 8x
#define TWSTRIDE  (NSTG * TSTG_FL)       // 6144 per warp
#define TV_OFF    (NW * TWSTRIDE)        // 49152
#define TBAR_FL   (TV_OFF + TSTG_FL)     // 51200 (bars after v)
#define TSMEM_BYTES (TBAR_FL * 4 + NW * NSTG * 8)   // 204800+192
#define BSTRIDE (C_N * P_N * F2)         // 36864 floats per B
#define V_ELEMS (8 * C_N * P_N * F2)
#define BIDX(pass, j) (((pass) == 1) ? (BPW - 1 - (j)) : (j))

__device__ __forceinline__ uint32_t s2u(const void* p) {
    return (uint32_t)__cvta_generic_to_shared(p);
}
__device__ __forceinline__ void mbar_init(uint32_t a, uint32_t cnt) {
    asm volatile("mbarrier.init.shared.b64 [%0], %1;" :: "r"(a), "r"(cnt) : "memory");
}
__device__ __forceinline__ void mbar_expect(uint32_t a, uint32_t tx) {
    asm volatile("mbarrier.arrive.expect_tx.shared.b64 _, [%0], %1;"
                 :: "r"(a), "r"(tx) : "memory");
}
__device__ __forceinline__ void mbar_wait(uint32_t a, uint32_t ph) {
    uint32_t done;
    asm volatile("{\n\t.reg .pred p;\n\t"
        "mbarrier.try_wait.parity.acquire.cta.shared::cta.b64 p, [%1], %2;\n\t"
        "selp.b32 %0, 1, 0, p;\n\t}"
        : "=r"(done) : "r"(a), "r"(ph) : "memory");
    if (!done) {
        asm volatile("{\n\t.reg .pred P1;\n\t"
            "WL_%=:\n\t"
            "mbarrier.try_wait.parity.acquire.cta.shared::cta.b64 P1, [%0], %1, 0x989680;\n\t"
            "@P1 bra.uni WD_%=;\n\t"
            "bra.uni WL_%=;\n\t"
            "WD_%=:\n\t}"
            :: "r"(a), "r"(ph) : "memory");
    }
}
__device__ __forceinline__ void tma4d(uint32_t dst, const CUtensorMap* m,
                                      int cx, int cC, int cp, int cB, uint32_t bar) {
    asm volatile(
        "cp.async.bulk.tensor.4d.shared::cta.global.tile.mbarrier::complete_tx::bytes "
        "[%0], [%1, {%2, %3, %4, %5}], [%6];"
        :: "r"(dst), "l"(m), "r"(cx), "r"(cC), "r"(cp), "r"(cB), "r"(bar)
        : "memory");
}

__global__ void __launch_bounds__(256, 1)
caps_route_tma(const __grid_constant__ CUtensorMap tmap, float* __restrict__ out) {
    extern __shared__ float sm[];
    float* v_s = sm + TV_OFF;
    const uint32_t smb = s2u(sm);
    const uint32_t bar0 = smb + 4u * TBAR_FL;

    const int t = threadIdx.x;
    const int w = t >> 5, lane = t & 31;
    const int Cc = lane & 15, zh = lane >> 4;
    const int b  = blockIdx.x / NTILE;
    const int x0 = (blockIdx.x % NTILE) * XT;
    const int Bbase = b * 144 + w * BPW;

    if (t == 0) {
#pragma unroll
        for (int i = 0; i < NW * NSTG; i++) mbar_init(bar0 + 8u * i, 1);
    }
    __syncthreads();

    const int ld = Cc * 8 + zh * 4;            // + p*128 in [p][C][x8]
    float* wst = sm + w * TWSTRIDE;            // warp stage base
    float* wpart = wst;                        // padded partials alias stages 0-1

#define ISSUE(pass_, j_)                                                     \
    do { if (lane == 0) {                                                    \
        int s_ = (j_) % NSTG;                                                \
        uint32_t ba_ = bar0 + 8u * (w * NSTG + s_);                          \
        mbar_expect(ba_, TSTG_FL * 4);                                       \
        tma4d(smb + 4u * (w * TWSTRIDE + s_ * TSTG_FL), &tmap,               \
              x0, 0, 0, Bbase + BIDX(pass_, j_), ba_);                       \
    } } while (0)
#define WAITC(j_) mbar_wait(bar0 + 8u * (w * NSTG + (j_) % NSTG),            \
                            (uint32_t)(((j_) / 3) & 1))

    for (int pass = 0; pass < 3; pass++) {
        float4 vreg[16];
        if (pass) {
#pragma unroll
            for (int p = 0; p < 16; p++)
                vreg[p] = *(const float4*)&v_s[p * 128 + ld];
        }
        float4 sreg[16];
#pragma unroll
        for (int p = 0; p < 16; p++) sreg[p] = make_float4(0.f, 0.f, 0.f, 0.f);

        ISSUE(pass, 0); ISSUE(pass, 1); ISSUE(pass, 2);

        if (pass == 0) {
            for (int j = 0; j < BPW; j++) {
                WAITC(j);
                const float* st = wst + (j % NSTG) * TSTG_FL + ld;
#pragma unroll
                for (int p = 0; p < 16; p++) {
                    float4 u4 = *(const float4*)&st[p * 128];
                    sreg[p].x += u4.x; sreg[p].y += u4.y;
                    sreg[p].z += u4.z; sreg[p].w += u4.w;
                }
                __syncwarp();
                if (j + 3 < BPW) ISSUE(pass, j + 3);
            }
        } else {
            WAITC(0);
            float4 d = make_float4(0.f, 0.f, 0.f, 0.f);
            {
                const float* st = wst + ld;
#pragma unroll
                for (int p = 0; p < 16; p++) {
                    float4 u4 = *(const float4*)&st[p * 128];
                    d.x = fmaf(u4.x, vreg[p].x, d.x);
                    d.y = fmaf(u4.y, vreg[p].y, d.y);
                    d.z = fmaf(u4.z, vreg[p].z, d.z);
                    d.w = fmaf(u4.w, vreg[p].w, d.w);
                }
            }
            for (int j = 0; j < BPW; j++) {
                float4 dn = make_float4(0.f, 0.f, 0.f, 0.f);
                if (j + 1 < BPW) {
                    WAITC(j + 1);
                    const float* stn = wst + ((j + 1) % NSTG) * TSTG_FL + ld;
#pragma unroll
                    for (int p = 0; p < 16; p++) {
                        float4 u4 = *(const float4*)&stn[p * 128];
                        dn.x = fmaf(u4.x, vreg[p].x, dn.x);
                        dn.y = fmaf(u4.y, vreg[p].y, dn.y);
                        dn.z = fmaf(u4.z, vreg[p].z, dn.z);
                        dn.w = fmaf(u4.w, vreg[p].w, dn.w);
                    }
                }
                float4 e = make_float4(__expf(d.x), __expf(d.y),
                                       __expf(d.z), __expf(d.w));
                float4 ss = e;
#pragma unroll
                for (int m = 1; m < 16; m <<= 1) {
                    ss.x += __shfl_xor_sync(0xffffffffu, ss.x, m);
                    ss.y += __shfl_xor_sync(0xffffffffu, ss.y, m);
                    ss.z += __shfl_xor_sync(0xffffffffu, ss.z, m);
                    ss.w += __shfl_xor_sync(0xffffffffu, ss.w, m);
                }
                float4 cc = make_float4(__fdividef(e.x, ss.x),
                                        __fdividef(e.y, ss.y),
                                        __fdividef(e.z, ss.z),
                                        __fdividef(e.w, ss.w));
                const float* st = wst + (j % NSTG) * TSTG_FL + ld;
#pragma unroll
                for (int p = 0; p < 16; p++) {
                    float4 u4 = *(const float4*)&st[p * 128];
                    sreg[p].x = fmaf(cc.x, u4.x, sreg[p].x);
                    sreg[p].y = fmaf(cc.y, u4.y, sreg[p].y);
                    sreg[p].z = fmaf(cc.z, u4.z, sreg[p].z);
                    sreg[p].w = fmaf(cc.w, u4.w, sreg[p].w);
                }
                __syncwarp();
                if (j + 3 < BPW) ISSUE(pass, j + 3);
                d = dn;
            }
        }

        // partials -> padded layout aliased on own stages (pipeline drained)
        if (pass == 0) {
#pragma unroll
            for (int p = 0; p < 16; p++) {
                sreg[p].x *= 0.0625f; sreg[p].y *= 0.0625f;
                sreg[p].z *= 0.0625f; sreg[p].w *= 0.0625f;
            }
        }
#pragma unroll
        for (int p = 0; p < 16; p++)
            *(float4*)&wpart[Cc * 132 + p * 8 + zh * 4] = sreg[p];
        __syncthreads();

        {   // squash: t = (Cc2 = t>>4, p2 = t&15)
            const int Cc2 = t >> 4, p2 = t & 15;
            const int roff = Cc2 * 132 + p2 * 8;
            float4 sa = make_float4(0.f, 0.f, 0.f, 0.f);
            float4 sb = make_float4(0.f, 0.f, 0.f, 0.f);
#pragma unroll
            for (int w2 = 0; w2 < NW; w2++) {
                float4 a4 = *(const float4*)&sm[w2 * TWSTRIDE + roff];
                float4 b4 = *(const float4*)&sm[w2 * TWSTRIDE + roff + 4];
                sa.x += a4.x; sa.y += a4.y; sa.z += a4.z; sa.w += a4.w;
                sb.x += b4.x; sb.y += b4.y; sb.z += b4.z; sb.w += b4.w;
            }
            float4 na = make_float4(sa.x * sa.x, sa.y * sa.y,
                                    sa.z * sa.z, sa.w * sa.w);
            float4 nb = make_float4(sb.x * sb.x, sb.y * sb.y,
                                    sb.z * sb.z, sb.w * sb.w);
#pragma unroll
            for (int m = 1; m < 16; m <<= 1) {
                na.x += __shfl_xor_sync(0xffffffffu, na.x, m);
                na.y += __shfl_xor_sync(0xffffffffu, na.y, m);
                na.z += __shfl_xor_sync(0xffffffffu, na.z, m);
                na.w += __shfl_xor_sync(0xffffffffu, na.w, m);
                nb.x += __shfl_xor_sync(0xffffffffu, nb.x, m);
                nb.y += __shfl_xor_sync(0xffffffffu, nb.y, m);
                nb.z += __shfl_xor_sync(0xffffffffu, nb.z, m);
                nb.w += __shfl_xor_sync(0xffffffffu, nb.w, m);
            }
            float4 ka = make_float4(sqrtf(na.x) / (1.f + na.x),
                                    sqrtf(na.y) / (1.f + na.y),
                                    sqrtf(na.z) / (1.f + na.z),
                                    sqrtf(na.w) / (1.f + na.w));
            float4 kb = make_float4(sqrtf(nb.x) / (1.f + nb.x),
                                    sqrtf(nb.y) / (1.f + nb.y),
                                    sqrtf(nb.z) / (1.f + nb.z),
                                    sqrtf(nb.w) / (1.f + nb.w));
            float4 va = make_float4(sa.x * ka.x, sa.y * ka.y,
                                    sa.z * ka.z, sa.w * ka.w);
            float4 vb = make_float4(sb.x * kb.x, sb.y * kb.y,
                                    sb.z * kb.z, sb.w * kb.w);
            const int voff = p2 * 128 + Cc2 * 8;   // [p][C][x8]

            if (pass < 2) {
                if (pass == 1) {
                    float4 oa = *(const float4*)&v_s[voff];
                    float4 ob = *(const float4*)&v_s[voff + 4];
                    va.x += oa.x; va.y += oa.y; va.z += oa.z; va.w += oa.w;
                    vb.x += ob.x; vb.y += ob.y; vb.z += ob.z; vb.w += ob.w;
                }
                *(float4*)&v_s[voff]     = va;
                *(float4*)&v_s[voff + 4] = vb;
            } else {
                float* og = out + (((size_t)(b * C_N + Cc2)) * P_N + p2) * F2 + x0;
                *(float4*)og       = va;
                *(float4*)(og + 4) = vb;
                if (p2 == 0) {
                    float* oa = out + (size_t)V_ELEMS
                              + ((size_t)(b * C_N + Cc2)) * F2 + x0;
                    *(float4*)oa = make_float4(na.x / (1.f + na.x),
                                               na.y / (1.f + na.y),
                                               na.z / (1.f + na.z),
                                               na.w / (1.f + na.w));
                    *(float4*)(oa + 4) = make_float4(nb.x / (1.f + nb.x),
                                                     nb.y / (1.f + nb.y),
                                                     nb.z / (1.f + nb.z),
                                                     nb.w / (1.f + nb.w));
                }
            }
        }
        __syncthreads();
    }
#undef ISSUE
#undef WAITC
}

// ======================= fallback: R13 kernel (verified 104.6us) =============
#define PLANE 132
#define STG_FL (C_N * PLANE)
#define WSTRIDE (NSTG * STG_FL)
#define U_FL  (NW * WSTRIDE)
#define V_OFF U_FL
#define SMEM_FL (U_FL + STG_FL)
#define SMEM_BYTES (SMEM_FL * 4)

__device__ __forceinline__ void cp_async16(uint32_t s, const float* g) {
    asm volatile("cp.async.cg.shared.global [%0], [%1], 16;" :: "r"(s), "l"(g));
}
__device__ __forceinline__ void prefetch_B(const float* __restrict__ gB,
                                           uint32_t dst, int lane) {
    const int pl = lane >> 1, h = lane & 1;
    const float* g = gB + (size_t)pl * F2 + h * 4;
    uint32_t d = dst + 4u * (pl * XT + h * 4);
#pragma unroll
    for (int k = 0; k < 16; k++)
        cp_async16(d + 4u * (k * PLANE), g + (size_t)k * (P_N * F2));
    asm volatile("cp.async.commit_group;");
}

__global__ void __launch_bounds__(256, 1)
caps_route_fb(const float* __restrict__ u, float* __restrict__ out) {
    extern __shared__ float sm[];
    const uint32_t smb = (uint32_t)__cvta_generic_to_shared(sm);
    float* v_s = sm + V_OFF;
    const int t = threadIdx.x;
    const int w = t >> 5, lane = t & 31;
    const int Cc = lane & 15, zh = lane >> 4;
    const int b  = blockIdx.x / NTILE;
    const int x0 = (blockIdx.x % NTILE) * XT;
    const float* ubW = u + ((size_t)b * 144 + w * BPW) * BSTRIDE + x0;
    const uint32_t wbase = smb + 4u * (w * WSTRIDE);
    float* wstage0 = sm + w * WSTRIDE;
    const int ld_off = Cc * PLANE + zh * 4;

    for (int pass = 0; pass < 3; pass++) {
        float4 vreg[16];
        if (pass) {
#pragma unroll
            for (int p = 0; p < 16; p++)
                vreg[p] = *(const float4*)&v_s[ld_off + p * 8];
        }
        float4 sreg[16];
#pragma unroll
        for (int p = 0; p < 16; p++) sreg[p] = make_float4(0.f, 0.f, 0.f, 0.f);

        prefetch_B(ubW + (size_t)BIDX(pass, 0) * BSTRIDE, wbase,               lane);
        prefetch_B(ubW + (size_t)BIDX(pass, 1) * BSTRIDE, wbase + 4u * STG_FL, lane);
        prefetch_B(ubW + (size_t)BIDX(pass, 2) * BSTRIDE, wbase + 8u * STG_FL, lane);

        if (pass == 0) {
            for (int j = 0; j < BPW; j++) {
                if      (j <= BPW - 3) asm volatile("cp.async.wait_group 2;");
                else if (j == BPW - 2) asm volatile("cp.async.wait_group 1;");
                else                   asm volatile("cp.async.wait_group 0;");
                __syncwarp();
                const float* st = sm + w * WSTRIDE + (j % NSTG) * STG_FL + ld_off;
#pragma unroll
                for (int p = 0; p < 16; p++) {
                    float4 u4 = *(const float4*)&st[p * 8];
                    sreg[p].x += u4.x; sreg[p].y += u4.y;
                    sreg[p].z += u4.z; sreg[p].w += u4.w;
                }
                if (j + 3 < BPW)
                    prefetch_B(ubW + (size_t)BIDX(pass, j + 3) * BSTRIDE,
                               wbase + 4u * ((j % NSTG) * STG_FL), lane);
            }
        } else {
            asm volatile("cp.async.wait_group 2;");
            __syncwarp();
            float4 d = make_float4(0.f, 0.f, 0.f, 0.f);
            {
                const float* st = sm + w * WSTRIDE + ld_off;
#pragma unroll
                for (int p = 0; p < 16; p++) {
                    float4 u4 = *(const float4*)&st[p * 8];
                    d.x = fmaf(u4.x, vreg[p].x, d.x);
                    d.y = fmaf(u4.y, vreg[p].y, d.y);
                    d.z = fmaf(u4.z, vreg[p].z, d.z);
                    d.w = fmaf(u4.w, vreg[p].w, d.w);
                }
            }
            for (int j = 0; j < BPW; j++) {
                float4 dn = make_float4(0.f, 0.f, 0.f, 0.f);
                if (j + 1 < BPW) {
                    if (j <= BPW - 3) asm volatile("cp.async.wait_group 1;");
                    else              asm volatile("cp.async.wait_group 0;");
                    __syncwarp();
                    const float* stn = sm + w * WSTRIDE
                                     + ((j + 1) % NSTG) * STG_FL + ld_off;
#pragma unroll
                    for (int p = 0; p < 16; p++) {
                        float4 u4 = *(const float4*)&stn[p * 8];
                        dn.x = fmaf(u4.x, vreg[p].x, dn.x);
                        dn.y = fmaf(u4.y, vreg[p].y, dn.y);
                        dn.z = fmaf(u4.z, vreg[p].z, dn.z);
                        dn.w = fmaf(u4.w, vreg[p].w, dn.w);
                    }
                }
                float4 e = make_float4(__expf(d.x), __expf(d.y),
                                       __expf(d.z), __expf(d.w));
                float4 ss = e;
#pragma unroll
                for (int m = 1; m < 16; m <<= 1) {
                    ss.x += __shfl_xor_sync(0xffffffffu, ss.x, m);
                    ss.y += __shfl_xor_sync(0xffffffffu, ss.y, m);
                    ss.z += __shfl_xor_sync(0xffffffffu, ss.z, m);
                    ss.w += __shfl_xor_sync(0xffffffffu, ss.w, m);
                }
                float4 cc = make_float4(__fdividef(e.x, ss.x),
                                        __fdividef(e.y, ss.y),
                                        __fdividef(e.z, ss.z),
                                        __fdividef(e.w, ss.w));
                const float* st = sm + w * WSTRIDE + (j % NSTG) * STG_FL + ld_off;
#pragma unroll
                for (int p = 0; p < 16; p++) {
                    float4 u4 = *(const float4*)&st[p * 8];
                    sreg[p].x = fmaf(cc.x, u4.x, sreg[p].x);
                    sreg[p].y = fmaf(cc.y, u4.y, sreg[p].y);
                    sreg[p].z = fmaf(cc.z, u4.z, sreg[p].z);
                    sreg[p].w = fmaf(cc.w, u4.w, sreg[p].w);
                }
                if (j + 3 < BPW)
                    prefetch_B(ubW + (size_t)BIDX(pass, j + 3) * BSTRIDE,
                               wbase + 4u * ((j % NSTG) * STG_FL), lane);
                d = dn;
            }
        }

        if (pass == 0) {
#pragma unroll
            for (int p = 0; p < 16; p++) {
                sreg[p].x *= 0.0625f; sreg[p].y *= 0.0625f;
                sreg[p].z *= 0.0625f; sreg[p].w *= 0.0625f;
            }
        }
#pragma unroll
        for (int p = 0; p < 16; p++)
            *(float4*)&wstage0[ld_off + p * 8] = sreg[p];
        __syncthreads();

        {
            const int Cc2 = t >> 4, p2 = t & 15;
            const int roff = Cc2 * PLANE + p2 * 8;
            float4 sa = make_float4(0.f, 0.f, 0.f, 0.f);
            float4 sb = make_float4(0.f, 0.f, 0.f, 0.f);
#pragma unroll
            for (int w2 = 0; w2 < NW; w2++) {
                float4 a4 = *(const float4*)&sm[w2 * WSTRIDE + roff];
                float4 b4 = *(const float4*)&sm[w2 * WSTRIDE + roff + 4];
                sa.x += a4.x; sa.y += a4.y; sa.z += a4.z; sa.w += a4.w;
                sb.x += b4.x; sb.y += b4.y; sb.z += b4.z; sb.w += b4.w;
            }
            float4 na = make_float4(sa.x * sa.x, sa.y * sa.y,
                                    sa.z * sa.z, sa.w * sa.w);
            float4 nb = make_float4(sb.x * sb.x, sb.y * sb.y,
                                    sb.z * sb.z, sb.w * sb.w);
#pragma unroll
            for (int m = 1; m < 16; m <<= 1) {
                na.x += __shfl_xor_sync(0xffffffffu, na.x, m);
                na.y += __shfl_xor_sync(0xffffffffu, na.y, m);
                na.z += __shfl_xor_sync(0xffffffffu, na.z, m);
                na.w += __shfl_xor_sync(0xffffffffu, na.w, m);
                nb.x += __shfl_xor_sync(0xffffffffu, nb.x, m);
                nb.y += __shfl_xor_sync(0xffffffffu, nb.y, m);
                nb.z += __shfl_xor_sync(0xffffffffu, nb.z, m);
                nb.w += __shfl_xor_sync(0xffffffffu, nb.w, m);
            }
            float4 ka = make_float4(sqrtf(na.x) / (1.f + na.x),
                                    sqrtf(na.y) / (1.f + na.y),
                                    sqrtf(na.z) / (1.f + na.z),
                                    sqrtf(na.w) / (1.f + na.w));
            float4 kb = make_float4(sqrtf(nb.x) / (1.f + nb.x),
                                    sqrtf(nb.y) / (1.f + nb.y),
                                    sqrtf(nb.z) / (1.f + nb.z),
                                    sqrtf(nb.w) / (1.f + nb.w));
            float4 va = make_float4(sa.x * ka.x, sa.y * ka.y,
                                    sa.z * ka.z, sa.w * ka.w);
            float4 vb = make_float4(sb.x * kb.x, sb.y * kb.y,
                                    sb.z * kb.z, sb.w * kb.w);
            if (pass < 2) {
                if (pass == 1) {
                    float4 oa = *(const float4*)&v_s[roff];
                    float4 ob = *(const float4*)&v_s[roff + 4];
                    va.x += oa.x; va.y += oa.y; va.z += oa.z; va.w += oa.w;
                    vb.x += ob.x; vb.y += ob.y; vb.z += ob.z; vb.w += ob.w;
                }
                *(float4*)&v_s[roff]     = va;
                *(float4*)&v_s[roff + 4] = vb;
            } else {
                float* og = out + (((size_t)(b * C_N + Cc2)) * P_N + p2) * F2 + x0;
                *(float4*)og       = va;
                *(float4*)(og + 4) = vb;
                if (p2 == 0) {
                    float* oa = out + (size_t)V_ELEMS
                              + ((size_t)(b * C_N + Cc2)) * F2 + x0;
                    *(float4*)oa = make_float4(na.x / (1.f + na.x),
                                               na.y / (1.f + na.y),
                                               na.z / (1.f + na.z),
                                               na.w / (1.f + na.w));
                    *(float4*)(oa + 4) = make_float4(nb.x / (1.f + nb.x),
                                                     nb.y / (1.f + nb.y),
                                                     nb.z / (1.f + nb.z),
                                                     nb.w / (1.f + nb.w));
                }
            }
        }
        __syncthreads();
    }
}

// =========================== host ===========================================
typedef CUresult (*EncodeTiledFn)(
    CUtensorMap*, CUtensorMapDataType, cuuint32_t, void*,
    const cuuint64_t*, const cuuint64_t*, const cuuint32_t*, const cuuint32_t*,
    CUtensorMapInterleave, CUtensorMapSwizzle, CUtensorMapL2promotion,
    CUtensorMapFloatOOBfill);

extern "C" void kernel_launch(void* const* d_in, const int* in_sizes, int n_in,
                              void* d_out, int out_size) {
    const float* u = (const float*)d_in[0];   // (8,144,16,16,12,12) f32
    float* out = (float*)d_out;

    static EncodeTiledFn enc =
        (EncodeTiledFn)dlsym(RTLD_DEFAULT, "cuTensorMapEncodeTiled");

    bool use_tma = false;
    CUtensorMap tmap;
    if (enc) {
        // 4D view: d0=x(144), d1=C(16, stride 9216B), d2=p(16, stride 576B),
        // d3=(b*144+B)(1152, stride 147456B); box (8,16,16,1) -> smem [p][C][x8]
        cuuint64_t dims[4]    = {144, 16, 16, 1152};
        cuuint64_t strides[3] = {2304ull * 4, 144ull * 4, 36864ull * 4};
        cuuint32_t box[4]     = {8, 16, 16, 1};
        cuuint32_t es[4]      = {1, 1, 1, 1};
        CUresult r = enc(&tmap, CU_TENSOR_MAP_DATA_TYPE_FLOAT32, 4, (void*)u,
                         dims, strides, box, es,
                         CU_TENSOR_MAP_INTERLEAVE_NONE, CU_TENSOR_MAP_SWIZZLE_NONE,
                         CU_TENSOR_MAP_L2_PROMOTION_NONE,
                         CU_TENSOR_MAP_FLOAT_OOB_FILL_NONE);
        use_tma = (r == CUDA_SUCCESS);
    }

    if (use_tma) {
        cudaFuncSetAttribute(caps_route_tma,
                             cudaFuncAttributeMaxDynamicSharedMemorySize,
                             TSMEM_BYTES);
        caps_route_tma<<<8 * NTILE, 256, TSMEM_BYTES>>>(tmap, out);
    } else {
        cudaFuncSetAttribute(caps_route_fb,
                             cudaFuncAttributeMaxDynamicSharedMemorySize,
                             SMEM_BYTES);
        caps_route_fb<<<8 * NTILE, 256, SMEM_BYTES>>>(u, out);
    }
}